// round 9
// baseline (speedup 1.0000x reference)
#include <cuda_runtime.h>
#include <cuda_bf16.h>
#include <math.h>
#include <stdint.h>

#define N_ROWS   4096
#define D_DIM    1024
#define TEMP_INV 20.0f
#define EPS_N    1e-8f
#define QS       512.0f                       // int8 quantization scale
#define DEQ      (TEMP_INV / (QS * QS))       // s32 -> logit

// GEMM tiling (int8; K in bytes == elements)
#define BM 128
#define BN 128
#define BK 64
#define NKC (D_DIM / BK)         // 16 chunks
#define NSTAGE 3
#define CT_N (2 * N_ROWS / BN)   // 64 col tiles
#define RT_N (N_ROWS / BM)       // 32 row tiles
#define ROWB 80                  // 64B data + 16B pad
#define NTHREADS 256

#define STAGE_BYTES ((BM + BN) * ROWB)       // 20480
#define SMEM_TOTAL  (NSTAGE * STAGE_BYTES)   // 61440
// sred aliases stage 0 after the post-mainloop barrier

// Scratch
__device__ uint8_t g_q[3][(size_t)N_ROWS * D_DIM];   // int8 bits
__device__ float g_partial[(size_t)N_ROWS * CT_N];
__device__ float g_diag[N_ROWS];
__device__ float g_rowloss[N_ROWS];

// ---------------------------------------------------------------------------
__device__ __forceinline__ uint32_t smem_u32(const void* p) {
    uint32_t a;
    asm("{ .reg .u64 t; cvta.to.shared.u64 t, %1; cvt.u32.u64 %0, t; }"
        : "=r"(a) : "l"(p));
    return a;
}

#define LDSM_X4(r, addr) \
    asm volatile("ldmatrix.sync.aligned.m8n8.x4.shared.b16 {%0,%1,%2,%3}, [%4];" \
                 : "=r"((r)[0]), "=r"((r)[1]), "=r"((r)[2]), "=r"((r)[3]) : "r"(addr))

#define MMA_S8(d, a, b) \
    asm volatile("mma.sync.aligned.m16n8k32.row.col.s32.s8.s8.s32 " \
                 "{%0,%1,%2,%3}, {%4,%5,%6,%7}, {%8,%9}, {%0,%1,%2,%3};" \
                 : "+r"((d)[0]), "+r"((d)[1]), "+r"((d)[2]), "+r"((d)[3]) \
                 : "r"((a)[0]), "r"((a)[1]), "r"((a)[2]), "r"((a)[3]), \
                   "r"((b)[0]), "r"((b)[1]))

#define CP_ASYNC16(so, gp) \
    asm volatile("cp.async.cg.shared.global [%0], [%1], 16;" \
                 :: "r"(so), "l"(__cvta_generic_to_global(gp)))
#define CP_COMMIT()  asm volatile("cp.async.commit_group;" ::: "memory")
#define CP_WAIT(n)   asm volatile("cp.async.wait_group %0;" :: "n"(n) : "memory")

// pack 4 floats -> 4 saturated s8 bytes (little-endian order x,y,z,w)
__device__ __forceinline__ uint32_t pack4_s8(float4 v) {
    int i0 = __float2int_rn(v.x);
    int i1 = __float2int_rn(v.y);
    int i2 = __float2int_rn(v.z);
    int i3 = __float2int_rn(v.w);
    uint32_t t, r;
    asm("cvt.pack.sat.s8.s32.b32 %0, %1, %2, %3;"
        : "=r"(t) : "r"(i3), "r"(i2), "r"(0u));
    asm("cvt.pack.sat.s8.s32.b32 %0, %1, %2, %3;"
        : "=r"(r) : "r"(i1), "r"(i0), "r"(t));
    return r;
}

// ---------------------------------------------------------------------------
// Kernel 1: row norms + normalize + int8 quantize (scale QS).
// ---------------------------------------------------------------------------
__global__ void __launch_bounds__(256) norm_convert_kernel(const float* __restrict__ x,
                                                           const float* __restrict__ t,
                                                           const float* __restrict__ h) {
    int warp = (blockIdx.x * blockDim.x + threadIdx.x) >> 5;
    int lane = threadIdx.x & 31;
    if (warp >= 3 * N_ROWS) return;
    int mat = warp / N_ROWS;
    int row = warp - mat * N_ROWS;
    const float* src = (mat == 0) ? x : (mat == 1 ? t : h);
    const float4* p = (const float4*)(src + (size_t)row * D_DIM);
    float4 v[8];
    float s = 0.f;
#pragma unroll
    for (int i = 0; i < 8; i++) {
        v[i] = p[lane + i * 32];
        s += v[i].x * v[i].x + v[i].y * v[i].y + v[i].z * v[i].z + v[i].w * v[i].w;
    }
#pragma unroll
    for (int o = 16; o; o >>= 1) s += __shfl_xor_sync(0xffffffffu, s, o);
    float inv = 1.0f / fmaxf(sqrtf(s), EPS_N);
    float sc = inv * QS;
    uint32_t* dst = (uint32_t*)(&g_q[mat][(size_t)row * D_DIM]);
#pragma unroll
    for (int i = 0; i < 8; i++) {
        float4 w;
        w.x = v[i].x * sc; w.y = v[i].y * sc; w.z = v[i].z * sc; w.w = v[i].w * sc;
        dst[lane + i * 32] = pack4_s8(w);
    }
}

// ---------------------------------------------------------------------------
// Kernel 2: s8 IMMA GEMM (s32 acc), CTA 128x128, 256 threads (2Mx4N warps),
// BK=64, 3-stage cp.async, 2 CTAs/SM, fused exp epilogue.
// ---------------------------------------------------------------------------
__global__ void __launch_bounds__(NTHREADS, 2) sim_s8_kernel() {
    extern __shared__ __align__(16) char dsm[];
    const int tid = threadIdx.x;
    const int lane = tid & 31;
    const int wid = tid >> 5;
    const int wm = wid & 1;            // 0..1 -> 64 rows
    const int wn = wid >> 1;           // 0..3 -> 32 cols

    const int ct = blockIdx.x;         // 0..63
    const int rt = blockIdx.y;         // 0..31
    const int rbase = rt * BM;
    const int cbase = ct * BN;
    const bool isNeg = (cbase >= N_ROWS);
    const uint8_t* Bmat = isNeg ? g_q[2] : g_q[1];
    const int cloc = isNeg ? (cbase - N_ROWS) : cbase;

    const uint8_t* Ag = g_q[0] + (size_t)rbase * D_DIM;
    const uint8_t* Bg = Bmat + (size_t)cloc * D_DIM;

    uint32_t aSm[2], aGo[2], bSm[2], bGo[2];
#pragma unroll
    for (int q = 0; q < 2; q++) {
        int slot = tid + q * NTHREADS;
        int r = slot >> 2, sg = (slot & 3) * 16;
        aSm[q] = (uint32_t)(r * ROWB + sg);
        aGo[q] = (uint32_t)(r * D_DIM + sg);
        bSm[q] = (uint32_t)(BM * ROWB + r * ROWB + sg);
        bGo[q] = (uint32_t)(r * D_DIM + sg);
    }
    uint32_t stageBase[NSTAGE];
#pragma unroll
    for (int s = 0; s < NSTAGE; s++) stageBase[s] = smem_u32(dsm + s * STAGE_BYTES);

#define LOAD_CHUNK(c, st)                                       \
    do {                                                        \
        const uint32_t k0 = (c) * BK;                           \
        const uint32_t sb_ = stageBase[st];                     \
        CP_ASYNC16(sb_ + aSm[0], Ag + aGo[0] + k0);             \
        CP_ASYNC16(sb_ + aSm[1], Ag + aGo[1] + k0);             \
        CP_ASYNC16(sb_ + bSm[0], Bg + bGo[0] + k0);             \
        CP_ASYNC16(sb_ + bSm[1], Bg + bGo[1] + k0);             \
        CP_COMMIT();                                            \
    } while (0)

    uint32_t acc[4][4][4];             // s32 accumulators
#pragma unroll
    for (int i = 0; i < 4; i++)
#pragma unroll
        for (int j = 0; j < 4; j++)
#pragma unroll
            for (int q = 0; q < 4; q++) acc[i][j][q] = 0u;

    LOAD_CHUNK(0, 0);
    LOAD_CHUNK(1, 1);

    // ldmatrix lane addressing (HW-verified rounds 3-8; 8-bit layouts identical)
    const int aRow = lane & 15;
    const int aSeg = (lane >> 4) * 16;
    const int bRow = ((lane >> 4) ? 8 : 0) + (lane & 7);
    const int bSeg = ((lane >> 3) & 1) * 16;

    for (int c = 0; c < NKC; c++) {
        CP_WAIT(1);
        __syncthreads();
        if (c + 2 < NKC) LOAD_CHUNK(c + 2, (c + 2) % 3);
        else CP_COMMIT();

        const uint32_t aB = stageBase[c % 3];
        const uint32_t bB = aB + BM * ROWB;
#pragma unroll
        for (int ks = 0; ks < 2; ks++) {
            const int kso = ks * 32;
            uint32_t afr[4][4], bfr[4][2];
#pragma unroll
            for (int mt = 0; mt < 4; mt++) {
                int row = wm * 64 + mt * 16 + aRow;
                LDSM_X4(afr[mt], aB + row * ROWB + kso + aSeg);
            }
#pragma unroll
            for (int np = 0; np < 2; np++) {
                int nrow = wn * 32 + np * 16 + bRow;
                uint32_t r_[4];
                LDSM_X4(r_, bB + nrow * ROWB + kso + bSeg);
                bfr[np * 2 + 0][0] = r_[0];
                bfr[np * 2 + 0][1] = r_[1];
                bfr[np * 2 + 1][0] = r_[2];
                bfr[np * 2 + 1][1] = r_[3];
            }
#pragma unroll
            for (int mt = 0; mt < 4; mt++)
#pragma unroll
                for (int nt = 0; nt < 4; nt++)
                    MMA_S8(acc[mt][nt], afr[mt], bfr[nt]);
        }
    }
    __syncthreads();                   // stage 0 reusable as sred

    // Epilogue: dequant, diag fixup, exp, per-row sums.
    const int g = lane >> 2;
    const int t2 = (lane & 3) * 2;
    const int diagOff = isNeg ? N_ROWS : 0;
    float* sred = (float*)dsm;

#pragma unroll
    for (int mt = 0; mt < 4; mt++) {
        const int gi0 = rbase + wm * 64 + mt * 16 + g;
        const int gi1 = gi0 + 8;
        const int d0 = gi0 + diagOff;
        const int d1 = gi1 + diagOff;
        float s0 = 0.f, s1 = 0.f;
#pragma unroll
        for (int nt = 0; nt < 4; nt++) {
            const int gc = cbase + wn * 32 + nt * 8 + t2;
            float v0 = (float)(int)acc[mt][nt][0] * DEQ;
            float v1 = (float)(int)acc[mt][nt][1] * DEQ;
            float v2 = (float)(int)acc[mt][nt][2] * DEQ;
            float v3 = (float)(int)acc[mt][nt][3] * DEQ;
            if (gc == d0)     { if (isNeg) v0 += 1.f; else g_diag[gi0] = v0; }
            if (gc + 1 == d0) { if (isNeg) v1 += 1.f; else g_diag[gi0] = v1; }
            if (gc == d1)     { if (isNeg) v2 += 1.f; else g_diag[gi1] = v2; }
            if (gc + 1 == d1) { if (isNeg) v3 += 1.f; else g_diag[gi1] = v3; }
            s0 += __expf(v0) + __expf(v1);
            s1 += __expf(v2) + __expf(v3);
        }
        s0 += __shfl_xor_sync(0xffffffffu, s0, 1);
        s0 += __shfl_xor_sync(0xffffffffu, s0, 2);
        s1 += __shfl_xor_sync(0xffffffffu, s1, 1);
        s1 += __shfl_xor_sync(0xffffffffu, s1, 2);
        if ((lane & 3) == 0) {
            sred[(wm * 64 + mt * 16 + g) * 4 + wn] = s0;
            sred[(wm * 64 + mt * 16 + g + 8) * 4 + wn] = s1;
        }
    }
    __syncthreads();
    if (tid < BM) {
        float s = sred[tid * 4] + sred[tid * 4 + 1] + sred[tid * 4 + 2] + sred[tid * 4 + 3];
        g_partial[(size_t)(rbase + tid) * CT_N + ct] = s;
    }
}

// ---------------------------------------------------------------------------
// Kernel 3a: per-row loss (1 thread/row)
// ---------------------------------------------------------------------------
__global__ void __launch_bounds__(256) rowloss_kernel() {
    const int row = blockIdx.x * 256 + threadIdx.x;
    const float4* p = (const float4*)&g_partial[(size_t)row * CT_N];
    float s = 0.f;
#pragma unroll
    for (int c = 0; c < CT_N / 4; c++) {
        float4 v = p[c];
        s += v.x + v.y + v.z + v.w;
    }
    g_rowloss[row] = logf(s) - g_diag[row];
}

// ---------------------------------------------------------------------------
// Kernel 3b: reduce row losses -> scalar mean
// ---------------------------------------------------------------------------
__global__ void __launch_bounds__(256) reduce_kernel(float* __restrict__ out) {
    __shared__ float sm[256];
    const int tid = threadIdx.x;
    const float4* p = (const float4*)g_rowloss;
    float local = 0.f;
#pragma unroll
    for (int i = 0; i < 4; i++) {
        float4 v = p[tid + i * 256];
        local += v.x + v.y + v.z + v.w;
    }
    sm[tid] = local;
    __syncthreads();
#pragma unroll
    for (int o = 128; o; o >>= 1) {
        if (tid < o) sm[tid] += sm[tid + o];
        __syncthreads();
    }
    if (tid == 0) out[0] = sm[0] * (1.0f / N_ROWS);
}

// ---------------------------------------------------------------------------
extern "C" void kernel_launch(void* const* d_in, const int* in_sizes, int n_in,
                              void* d_out, int out_size) {
    const float* x = (const float*)d_in[0];
    const float* t = (const float*)d_in[1];
    const float* h = (const float*)d_in[2];
    float* out = (float*)d_out;

    cudaFuncSetAttribute(sim_s8_kernel,
                         cudaFuncAttributeMaxDynamicSharedMemorySize, SMEM_TOTAL);

    norm_convert_kernel<<<(3 * N_ROWS) / 8, 256>>>(x, t, h);

    dim3 grid(CT_N, RT_N);
    sim_s8_kernel<<<grid, NTHREADS, SMEM_TOTAL>>>();

    rowloss_kernel<<<N_ROWS / 256, 256>>>();
    reduce_kernel<<<1, 256>>>(out);
}

// round 10
// speedup vs baseline: 2.5024x; 2.5024x over previous
#include <cuda_runtime.h>
#include <cuda_bf16.h>
#include <cuda_fp16.h>
#include <math.h>
#include <stdint.h>

#define N_ROWS   4096
#define D_DIM    1024
#define TEMP_INV 20.0f
#define EPS_N    1e-8f
#define QSCALE   16.0f
#define ISC2     (1.0f / (QSCALE * QSCALE))

// GEMM tiling (fp8 e4m3; K in bytes == elements) — round-7 proven config
#define BM 128
#define BN 128
#define BK 128
#define NKC (D_DIM / BK)         // 8 chunks
#define NSTAGE 3
#define CT_N (2 * N_ROWS / BN)   // 64 col tiles
#define RT_N (N_ROWS / BM)       // 32 row tiles
#define ROWB 144                 // 128B data + 16B pad
#define NTHREADS 256

#define STAGE_BYTES ((BM + BN) * ROWB)             // 36864
#define SM_SRED     (NSTAGE * STAGE_BYTES)         // 110592
#define SMEM_TOTAL  (SM_SRED + BM * 4 * 4)         // 112640 (2 CTAs/SM)

// Scratch
__device__ uint8_t g_q[3][(size_t)N_ROWS * D_DIM];
__device__ float g_partial[(size_t)N_ROWS * CT_N];
__device__ float g_diag[N_ROWS];
__device__ float g_blocksum[16];

// ---------------------------------------------------------------------------
__device__ __forceinline__ uint32_t smem_u32(const void* p) {
    uint32_t a;
    asm("{ .reg .u64 t; cvta.to.shared.u64 t, %1; cvt.u32.u64 %0, t; }"
        : "=r"(a) : "l"(p));
    return a;
}

#define LDSM_X4(r, addr) \
    asm volatile("ldmatrix.sync.aligned.m8n8.x4.shared.b16 {%0,%1,%2,%3}, [%4];" \
                 : "=r"((r)[0]), "=r"((r)[1]), "=r"((r)[2]), "=r"((r)[3]) : "r"(addr))

#define MMA_FP8_H(d, a, b) \
    asm volatile("mma.sync.aligned.m16n8k32.row.col.f16.e4m3.e4m3.f16 " \
                 "{%0,%1}, {%2,%3,%4,%5}, {%6,%7}, {%0,%1};" \
                 : "+r"((d)[0]), "+r"((d)[1]) \
                 : "r"((a)[0]), "r"((a)[1]), "r"((a)[2]), "r"((a)[3]), \
                   "r"((b)[0]), "r"((b)[1]))

#define CP_ASYNC16(so, gp) \
    asm volatile("cp.async.cg.shared.global [%0], [%1], 16;" \
                 :: "r"(so), "l"(__cvta_generic_to_global(gp)))
#define CP_COMMIT()  asm volatile("cp.async.commit_group;" ::: "memory")
#define CP_WAIT(n)   asm volatile("cp.async.wait_group %0;" :: "n"(n) : "memory")

__device__ __forceinline__ uint32_t pack4_e4m3(float4 v) {
    uint16_t lo, hi;
    asm("cvt.rn.satfinite.e4m3x2.f32 %0, %1, %2;" : "=h"(lo) : "f"(v.y), "f"(v.x));
    asm("cvt.rn.satfinite.e4m3x2.f32 %0, %1, %2;" : "=h"(hi) : "f"(v.w), "f"(v.z));
    return (uint32_t)lo | ((uint32_t)hi << 16);
}

// ---------------------------------------------------------------------------
// Kernel 1: block-per-row normalize + fp8 convert. 128 threads, ~30 regs,
// full occupancy. 3*4096 blocks.
// ---------------------------------------------------------------------------
__global__ void __launch_bounds__(128) norm_convert_kernel(const float* __restrict__ x,
                                                           const float* __restrict__ t,
                                                           const float* __restrict__ h) {
    __shared__ float sm[4];
    const int blk = blockIdx.x;
    const int mat = blk >> 12;             // / 4096
    const int row = blk & (N_ROWS - 1);
    const int tid = threadIdx.x;
    const int lane = tid & 31;
    const int wrp = tid >> 5;

    const float* src = (mat == 0) ? x : (mat == 1 ? t : h);
    const float4* p = (const float4*)(src + (size_t)row * D_DIM);

    float4 v0 = p[tid];
    float4 v1 = p[tid + 128];
    float s = v0.x * v0.x + v0.y * v0.y + v0.z * v0.z + v0.w * v0.w
            + v1.x * v1.x + v1.y * v1.y + v1.z * v1.z + v1.w * v1.w;
#pragma unroll
    for (int o = 16; o; o >>= 1) s += __shfl_xor_sync(0xffffffffu, s, o);
    if (lane == 0) sm[wrp] = s;
    __syncthreads();
    float tot = sm[0] + sm[1] + sm[2] + sm[3];
    float inv = 1.0f / fmaxf(sqrtf(tot), EPS_N);
    float sc = ((mat == 0) ? inv * TEMP_INV : inv) * QSCALE;

    uint32_t* dst = (uint32_t*)(&g_q[mat][(size_t)row * D_DIM]);
    float4 w0, w1;
    w0.x = v0.x * sc; w0.y = v0.y * sc; w0.z = v0.z * sc; w0.w = v0.w * sc;
    w1.x = v1.x * sc; w1.y = v1.y * sc; w1.z = v1.z * sc; w1.w = v1.w * sc;
    dst[tid] = pack4_e4m3(w0);
    dst[tid + 128] = pack4_e4m3(w1);
}

// ---------------------------------------------------------------------------
// Kernel 2: e4m3 GEMM (f16 acc), CTA 128x128, 256 threads (2Mx4N warps),
// BK=128, 3-stage cp.async, fragment double-buffering, 2 CTAs/SM. (round 7)
// ---------------------------------------------------------------------------
__global__ void __launch_bounds__(NTHREADS, 2) sim_fp8_kernel() {
    extern __shared__ __align__(16) char dsm[];
    const int tid = threadIdx.x;
    const int lane = tid & 31;
    const int wid = tid >> 5;
    const int wm = wid & 1;            // 0..1 -> 64 rows
    const int wn = wid >> 1;           // 0..3 -> 32 cols

    const int ct = blockIdx.x;         // 0..63
    const int rt = blockIdx.y;         // 0..31
    const int rbase = rt * BM;
    const int cbase = ct * BN;
    const bool isNeg = (cbase >= N_ROWS);
    const uint8_t* Bmat = isNeg ? g_q[2] : g_q[1];
    const int cloc = isNeg ? (cbase - N_ROWS) : cbase;

    const uint8_t* Ag = g_q[0] + (size_t)rbase * D_DIM;
    const uint8_t* Bg = Bmat + (size_t)cloc * D_DIM;

    uint32_t aSm[4], aGo[4], bSm[4], bGo[4];
#pragma unroll
    for (int q = 0; q < 4; q++) {
        int slot = tid + q * NTHREADS;
        int r = slot >> 3, sg = (slot & 7) * 16;
        aSm[q] = (uint32_t)(r * ROWB + sg);
        aGo[q] = (uint32_t)(r * D_DIM + sg);
        bSm[q] = (uint32_t)(BM * ROWB + r * ROWB + sg);
        bGo[q] = (uint32_t)(r * D_DIM + sg);
    }
    uint32_t stageBase[NSTAGE];
#pragma unroll
    for (int s = 0; s < NSTAGE; s++) stageBase[s] = smem_u32(dsm + s * STAGE_BYTES);

#define LOAD_CHUNK(c, st)                                       \
    do {                                                        \
        const uint32_t k0 = (c) * BK;                           \
        const uint32_t sb_ = stageBase[st];                     \
        CP_ASYNC16(sb_ + aSm[0], Ag + aGo[0] + k0);             \
        CP_ASYNC16(sb_ + aSm[1], Ag + aGo[1] + k0);             \
        CP_ASYNC16(sb_ + aSm[2], Ag + aGo[2] + k0);             \
        CP_ASYNC16(sb_ + aSm[3], Ag + aGo[3] + k0);             \
        CP_ASYNC16(sb_ + bSm[0], Bg + bGo[0] + k0);             \
        CP_ASYNC16(sb_ + bSm[1], Bg + bGo[1] + k0);             \
        CP_ASYNC16(sb_ + bSm[2], Bg + bGo[2] + k0);             \
        CP_ASYNC16(sb_ + bSm[3], Bg + bGo[3] + k0);             \
        CP_COMMIT();                                            \
    } while (0)

    uint32_t acc[4][4][2];
#pragma unroll
    for (int i = 0; i < 4; i++)
#pragma unroll
        for (int j = 0; j < 4; j++) { acc[i][j][0] = 0u; acc[i][j][1] = 0u; }

    LOAD_CHUNK(0, 0);
    LOAD_CHUNK(1, 1);

    const int aRow = lane & 15;
    const int aSeg = (lane >> 4) * 16;
    const int bRow = ((lane >> 4) ? 8 : 0) + (lane & 7);
    const int bSeg = ((lane >> 3) & 1) * 16;

    uint32_t afr[2][4][4], bfr[2][4][2];

#define LOAD_FRAGS(buf_, base_, kso_)                                        \
    do {                                                                     \
        _Pragma("unroll")                                                    \
        for (int mt = 0; mt < 4; mt++) {                                     \
            int row = wm * 64 + mt * 16 + aRow;                              \
            LDSM_X4(afr[buf_][mt], (base_) + row * ROWB + (kso_) + aSeg);    \
        }                                                                    \
        _Pragma("unroll")                                                    \
        for (int np = 0; np < 2; np++) {                                     \
            int nrow = wn * 32 + np * 16 + bRow;                             \
            uint32_t r_[4];                                                  \
            LDSM_X4(r_, (base_) + BM * ROWB + nrow * ROWB + (kso_) + bSeg);  \
            bfr[buf_][np * 2 + 0][0] = r_[0];                                \
            bfr[buf_][np * 2 + 0][1] = r_[1];                                \
            bfr[buf_][np * 2 + 1][0] = r_[2];                                \
            bfr[buf_][np * 2 + 1][1] = r_[3];                                \
        }                                                                    \
    } while (0)

    for (int c = 0; c < NKC; c++) {
        CP_WAIT(1);
        __syncthreads();
        if (c + 2 < NKC) LOAD_CHUNK(c + 2, (c + 2) % 3);
        else CP_COMMIT();

        const uint32_t sBase = stageBase[c % 3];
        LOAD_FRAGS(0, sBase, 0);
#pragma unroll
        for (int ks = 0; ks < 4; ks++) {
            const int cur = ks & 1;
            if (ks < 3) LOAD_FRAGS(cur ^ 1, sBase, (ks + 1) * 32);
#pragma unroll
            for (int mt = 0; mt < 4; mt++)
#pragma unroll
                for (int nt = 0; nt < 4; nt++)
                    MMA_FP8_H(acc[mt][nt], afr[cur][mt], bfr[cur][nt]);
        }
    }

    // Epilogue
    const int g = lane >> 2;
    const int t2 = (lane & 3) * 2;
    const int diagOff = isNeg ? N_ROWS : 0;
    float* sred = (float*)(dsm + SM_SRED);

#pragma unroll
    for (int mt = 0; mt < 4; mt++) {
        const int gi0 = rbase + wm * 64 + mt * 16 + g;
        const int gi1 = gi0 + 8;
        const int d0 = gi0 + diagOff;
        const int d1 = gi1 + diagOff;
        float s0 = 0.f, s1 = 0.f;
#pragma unroll
        for (int nt = 0; nt < 4; nt++) {
            const int gc = cbase + wn * 32 + nt * 8 + t2;
            __half2 lo = *(__half2*)&acc[mt][nt][0];
            __half2 hi = *(__half2*)&acc[mt][nt][1];
            float v0 = __half2float(lo.x) * ISC2;
            float v1 = __half2float(lo.y) * ISC2;
            float v2 = __half2float(hi.x) * ISC2;
            float v3 = __half2float(hi.y) * ISC2;
            if (gc == d0)     { if (isNeg) v0 += 1.f; else g_diag[gi0] = v0; }
            if (gc + 1 == d0) { if (isNeg) v1 += 1.f; else g_diag[gi0] = v1; }
            if (gc == d1)     { if (isNeg) v2 += 1.f; else g_diag[gi1] = v2; }
            if (gc + 1 == d1) { if (isNeg) v3 += 1.f; else g_diag[gi1] = v3; }
            s0 += __expf(v0) + __expf(v1);
            s1 += __expf(v2) + __expf(v3);
        }
        s0 += __shfl_xor_sync(0xffffffffu, s0, 1);
        s0 += __shfl_xor_sync(0xffffffffu, s0, 2);
        s1 += __shfl_xor_sync(0xffffffffu, s1, 1);
        s1 += __shfl_xor_sync(0xffffffffu, s1, 2);
        if ((lane & 3) == 0) {
            sred[(wm * 64 + mt * 16 + g) * 4 + wn] = s0;
            sred[(wm * 64 + mt * 16 + g + 8) * 4 + wn] = s1;
        }
    }
    __syncthreads();
    if (tid < BM) {
        float s = sred[tid * 4] + sred[tid * 4 + 1] + sred[tid * 4 + 2] + sred[tid * 4 + 3];
        g_partial[(size_t)(rbase + tid) * CT_N + ct] = s;
    }
}

// ---------------------------------------------------------------------------
// Kernel 3a: per-row loss + block reduction -> 16 partial sums
// ---------------------------------------------------------------------------
__global__ void __launch_bounds__(256) rowloss_kernel() {
    __shared__ float sm[256];
    const int tid = threadIdx.x;
    const int row = blockIdx.x * 256 + tid;
    const float4* p = (const float4*)&g_partial[(size_t)row * CT_N];
    float s = 0.f;
#pragma unroll
    for (int c = 0; c < CT_N / 4; c++) {
        float4 v = p[c];
        s += v.x + v.y + v.z + v.w;
    }
    sm[tid] = logf(s) - g_diag[row];
    __syncthreads();
#pragma unroll
    for (int o = 128; o; o >>= 1) {
        if (tid < o) sm[tid] += sm[tid + o];
        __syncthreads();
    }
    if (tid == 0) g_blocksum[blockIdx.x] = sm[0];
}

// ---------------------------------------------------------------------------
// Kernel 3b: 32-thread final reduce of 16 partials
// ---------------------------------------------------------------------------
__global__ void __launch_bounds__(32) reduce_kernel(float* __restrict__ out) {
    const int lane = threadIdx.x;
    float v = (lane < 16) ? g_blocksum[lane] : 0.f;
#pragma unroll
    for (int o = 8; o; o >>= 1) v += __shfl_xor_sync(0xffffffffu, v, o);
    if (lane == 0) out[0] = v * (1.0f / N_ROWS);
}

// ---------------------------------------------------------------------------
extern "C" void kernel_launch(void* const* d_in, const int* in_sizes, int n_in,
                              void* d_out, int out_size) {
    const float* x = (const float*)d_in[0];
    const float* t = (const float*)d_in[1];
    const float* h = (const float*)d_in[2];
    float* out = (float*)d_out;

    cudaFuncSetAttribute(sim_fp8_kernel,
                         cudaFuncAttributeMaxDynamicSharedMemorySize, SMEM_TOTAL);

    norm_convert_kernel<<<3 * N_ROWS, 128>>>(x, t, h);

    dim3 grid(CT_N, RT_N);
    sim_fp8_kernel<<<grid, NTHREADS, SMEM_TOTAL>>>();

    rowloss_kernel<<<N_ROWS / 256, 256>>>();
    reduce_kernel<<<1, 32>>>(out);
}

// round 11
// speedup vs baseline: 2.5261x; 1.0095x over previous
#include <cuda_runtime.h>
#include <cuda_bf16.h>
#include <cuda_fp16.h>
#include <math.h>
#include <stdint.h>

#define N_ROWS   4096
#define D_DIM    1024
#define TEMP_INV 20.0f
#define EPS_N    1e-8f
#define QSCALE   16.0f
#define ISC2     (1.0f / (QSCALE * QSCALE))

// GEMM tiling (fp8 e4m3; K in bytes == elements) — round-7 proven config
#define BM 128
#define BN 128
#define BK 128
#define NKC (D_DIM / BK)         // 8 chunks
#define NSTAGE 3
#define CT_N (2 * N_ROWS / BN)   // 64 col tiles
#define RT_N (N_ROWS / BM)       // 32 row tiles
#define ROWB 144                 // 128B data + 16B pad
#define NTHREADS 256

#define STAGE_BYTES ((BM + BN) * ROWB)             // 36864
#define SM_SRED     (NSTAGE * STAGE_BYTES)         // 110592
#define SMEM_TOTAL  (SM_SRED + BM * 4 * 4)         // 112640 (2 CTAs/SM)

// Scratch
__device__ uint8_t g_q[3][(size_t)N_ROWS * D_DIM];
__device__ float g_partial[(size_t)N_ROWS * CT_N];
__device__ float g_diag[N_ROWS];
__device__ float g_blocksum[16];
__device__ unsigned int g_ticket;    // zero-init; self-resetting each replay

// ---------------------------------------------------------------------------
__device__ __forceinline__ uint32_t smem_u32(const void* p) {
    uint32_t a;
    asm("{ .reg .u64 t; cvta.to.shared.u64 t, %1; cvt.u32.u64 %0, t; }"
        : "=r"(a) : "l"(p));
    return a;
}

#define LDSM_X4(r, addr) \
    asm volatile("ldmatrix.sync.aligned.m8n8.x4.shared.b16 {%0,%1,%2,%3}, [%4];" \
                 : "=r"((r)[0]), "=r"((r)[1]), "=r"((r)[2]), "=r"((r)[3]) : "r"(addr))

#define MMA_FP8_H(d, a, b) \
    asm volatile("mma.sync.aligned.m16n8k32.row.col.f16.e4m3.e4m3.f16 " \
                 "{%0,%1}, {%2,%3,%4,%5}, {%6,%7}, {%0,%1};" \
                 : "+r"((d)[0]), "+r"((d)[1]) \
                 : "r"((a)[0]), "r"((a)[1]), "r"((a)[2]), "r"((a)[3]), \
                   "r"((b)[0]), "r"((b)[1]))

#define CP_ASYNC16(so, gp) \
    asm volatile("cp.async.cg.shared.global [%0], [%1], 16;" \
                 :: "r"(so), "l"(__cvta_generic_to_global(gp)))
#define CP_COMMIT()  asm volatile("cp.async.commit_group;" ::: "memory")
#define CP_WAIT(n)   asm volatile("cp.async.wait_group %0;" :: "n"(n) : "memory")

__device__ __forceinline__ uint32_t pack4_e4m3(float4 v) {
    uint16_t lo, hi;
    asm("cvt.rn.satfinite.e4m3x2.f32 %0, %1, %2;" : "=h"(lo) : "f"(v.y), "f"(v.x));
    asm("cvt.rn.satfinite.e4m3x2.f32 %0, %1, %2;" : "=h"(hi) : "f"(v.w), "f"(v.z));
    return (uint32_t)lo | ((uint32_t)hi << 16);
}

// ---------------------------------------------------------------------------
// Kernel 1: warp-per-row normalize (+ 1/TEMP into x) + fp8 convert (round 7).
// ---------------------------------------------------------------------------
__global__ void __launch_bounds__(256) norm_convert_kernel(const float* __restrict__ x,
                                                           const float* __restrict__ t,
                                                           const float* __restrict__ h) {
    int warp = (blockIdx.x * blockDim.x + threadIdx.x) >> 5;
    int lane = threadIdx.x & 31;
    if (warp >= 3 * N_ROWS) return;
    int mat = warp / N_ROWS;
    int row = warp - mat * N_ROWS;
    const float* src = (mat == 0) ? x : (mat == 1 ? t : h);
    const float4* p = (const float4*)(src + (size_t)row * D_DIM);
    float4 v[8];
    float s = 0.f;
#pragma unroll
    for (int i = 0; i < 8; i++) {
        v[i] = p[lane + i * 32];
        s += v[i].x * v[i].x + v[i].y * v[i].y + v[i].z * v[i].z + v[i].w * v[i].w;
    }
#pragma unroll
    for (int o = 16; o; o >>= 1) s += __shfl_xor_sync(0xffffffffu, s, o);
    float inv = 1.0f / fmaxf(sqrtf(s), EPS_N);
    float sc = ((mat == 0) ? inv * TEMP_INV : inv) * QSCALE;
    uint32_t* dst = (uint32_t*)(&g_q[mat][(size_t)row * D_DIM]);
#pragma unroll
    for (int i = 0; i < 8; i++) {
        float4 w;
        w.x = v[i].x * sc; w.y = v[i].y * sc; w.z = v[i].z * sc; w.w = v[i].w * sc;
        dst[lane + i * 32] = pack4_e4m3(w);
    }
}

// ---------------------------------------------------------------------------
// Kernel 2: e4m3 GEMM (f16 acc), CTA 128x128, 256 threads (2Mx4N warps),
// BK=128, 3-stage cp.async, fragment double-buffering, 2 CTAs/SM. (round 7)
// ---------------------------------------------------------------------------
__global__ void __launch_bounds__(NTHREADS, 2) sim_fp8_kernel() {
    extern __shared__ __align__(16) char dsm[];
    const int tid = threadIdx.x;
    const int lane = tid & 31;
    const int wid = tid >> 5;
    const int wm = wid & 1;            // 0..1 -> 64 rows
    const int wn = wid >> 1;           // 0..3 -> 32 cols

    const int ct = blockIdx.x;         // 0..63
    const int rt = blockIdx.y;         // 0..31
    const int rbase = rt * BM;
    const int cbase = ct * BN;
    const bool isNeg = (cbase >= N_ROWS);
    const uint8_t* Bmat = isNeg ? g_q[2] : g_q[1];
    const int cloc = isNeg ? (cbase - N_ROWS) : cbase;

    const uint8_t* Ag = g_q[0] + (size_t)rbase * D_DIM;
    const uint8_t* Bg = Bmat + (size_t)cloc * D_DIM;

    uint32_t aSm[4], aGo[4], bSm[4], bGo[4];
#pragma unroll
    for (int q = 0; q < 4; q++) {
        int slot = tid + q * NTHREADS;
        int r = slot >> 3, sg = (slot & 7) * 16;
        aSm[q] = (uint32_t)(r * ROWB + sg);
        aGo[q] = (uint32_t)(r * D_DIM + sg);
        bSm[q] = (uint32_t)(BM * ROWB + r * ROWB + sg);
        bGo[q] = (uint32_t)(r * D_DIM + sg);
    }
    uint32_t stageBase[NSTAGE];
#pragma unroll
    for (int s = 0; s < NSTAGE; s++) stageBase[s] = smem_u32(dsm + s * STAGE_BYTES);

#define LOAD_CHUNK(c, st)                                       \
    do {                                                        \
        const uint32_t k0 = (c) * BK;                           \
        const uint32_t sb_ = stageBase[st];                     \
        CP_ASYNC16(sb_ + aSm[0], Ag + aGo[0] + k0);             \
        CP_ASYNC16(sb_ + aSm[1], Ag + aGo[1] + k0);             \
        CP_ASYNC16(sb_ + aSm[2], Ag + aGo[2] + k0);             \
        CP_ASYNC16(sb_ + aSm[3], Ag + aGo[3] + k0);             \
        CP_ASYNC16(sb_ + bSm[0], Bg + bGo[0] + k0);             \
        CP_ASYNC16(sb_ + bSm[1], Bg + bGo[1] + k0);             \
        CP_ASYNC16(sb_ + bSm[2], Bg + bGo[2] + k0);             \
        CP_ASYNC16(sb_ + bSm[3], Bg + bGo[3] + k0);             \
        CP_COMMIT();                                            \
    } while (0)

    uint32_t acc[4][4][2];
#pragma unroll
    for (int i = 0; i < 4; i++)
#pragma unroll
        for (int j = 0; j < 4; j++) { acc[i][j][0] = 0u; acc[i][j][1] = 0u; }

    LOAD_CHUNK(0, 0);
    LOAD_CHUNK(1, 1);

    const int aRow = lane & 15;
    const int aSeg = (lane >> 4) * 16;
    const int bRow = ((lane >> 4) ? 8 : 0) + (lane & 7);
    const int bSeg = ((lane >> 3) & 1) * 16;

    uint32_t afr[2][4][4], bfr[2][4][2];

#define LOAD_FRAGS(buf_, base_, kso_)                                        \
    do {                                                                     \
        _Pragma("unroll")                                                    \
        for (int mt = 0; mt < 4; mt++) {                                     \
            int row = wm * 64 + mt * 16 + aRow;                              \
            LDSM_X4(afr[buf_][mt], (base_) + row * ROWB + (kso_) + aSeg);    \
        }                                                                    \
        _Pragma("unroll")                                                    \
        for (int np = 0; np < 2; np++) {                                     \
            int nrow = wn * 32 + np * 16 + bRow;                             \
            uint32_t r_[4];                                                  \
            LDSM_X4(r_, (base_) + BM * ROWB + nrow * ROWB + (kso_) + bSeg);  \
            bfr[buf_][np * 2 + 0][0] = r_[0];                                \
            bfr[buf_][np * 2 + 0][1] = r_[1];                                \
            bfr[buf_][np * 2 + 1][0] = r_[2];                                \
            bfr[buf_][np * 2 + 1][1] = r_[3];                                \
        }                                                                    \
    } while (0)

    for (int c = 0; c < NKC; c++) {
        CP_WAIT(1);
        __syncthreads();
        if (c + 2 < NKC) LOAD_CHUNK(c + 2, (c + 2) % 3);
        else CP_COMMIT();

        const uint32_t sBase = stageBase[c % 3];
        LOAD_FRAGS(0, sBase, 0);
#pragma unroll
        for (int ks = 0; ks < 4; ks++) {
            const int cur = ks & 1;
            if (ks < 3) LOAD_FRAGS(cur ^ 1, sBase, (ks + 1) * 32);
#pragma unroll
            for (int mt = 0; mt < 4; mt++)
#pragma unroll
                for (int nt = 0; nt < 4; nt++)
                    MMA_FP8_H(acc[mt][nt], afr[cur][mt], bfr[cur][nt]);
        }
    }

    // Epilogue
    const int g = lane >> 2;
    const int t2 = (lane & 3) * 2;
    const int diagOff = isNeg ? N_ROWS : 0;
    float* sred = (float*)(dsm + SM_SRED);

#pragma unroll
    for (int mt = 0; mt < 4; mt++) {
        const int gi0 = rbase + wm * 64 + mt * 16 + g;
        const int gi1 = gi0 + 8;
        const int d0 = gi0 + diagOff;
        const int d1 = gi1 + diagOff;
        float s0 = 0.f, s1 = 0.f;
#pragma unroll
        for (int nt = 0; nt < 4; nt++) {
            const int gc = cbase + wn * 32 + nt * 8 + t2;
            __half2 lo = *(__half2*)&acc[mt][nt][0];
            __half2 hi = *(__half2*)&acc[mt][nt][1];
            float v0 = __half2float(lo.x) * ISC2;
            float v1 = __half2float(lo.y) * ISC2;
            float v2 = __half2float(hi.x) * ISC2;
            float v3 = __half2float(hi.y) * ISC2;
            if (gc == d0)     { if (isNeg) v0 += 1.f; else g_diag[gi0] = v0; }
            if (gc + 1 == d0) { if (isNeg) v1 += 1.f; else g_diag[gi0] = v1; }
            if (gc == d1)     { if (isNeg) v2 += 1.f; else g_diag[gi1] = v2; }
            if (gc + 1 == d1) { if (isNeg) v3 += 1.f; else g_diag[gi1] = v3; }
            s0 += __expf(v0) + __expf(v1);
            s1 += __expf(v2) + __expf(v3);
        }
        s0 += __shfl_xor_sync(0xffffffffu, s0, 1);
        s0 += __shfl_xor_sync(0xffffffffu, s0, 2);
        s1 += __shfl_xor_sync(0xffffffffu, s1, 1);
        s1 += __shfl_xor_sync(0xffffffffu, s1, 2);
        if ((lane & 3) == 0) {
            sred[(wm * 64 + mt * 16 + g) * 4 + wn] = s0;
            sred[(wm * 64 + mt * 16 + g + 8) * 4 + wn] = s1;
        }
    }
    __syncthreads();
    if (tid < BM) {
        float s = sred[tid * 4] + sred[tid * 4 + 1] + sred[tid * 4 + 2] + sred[tid * 4 + 3];
        g_partial[(size_t)(rbase + tid) * CT_N + ct] = s;
    }
}

// ---------------------------------------------------------------------------
// Kernel 3: fused per-row loss + final reduction (self-resetting ticket).
// 16 blocks; the last-arriving block sums the 16 partials in index order.
// ---------------------------------------------------------------------------
__global__ void __launch_bounds__(256) rowloss_kernel(float* __restrict__ out) {
    __shared__ float sm[256];
    __shared__ bool amLast;
    const int tid = threadIdx.x;
    const int row = blockIdx.x * 256 + tid;
    const float4* p = (const float4*)&g_partial[(size_t)row * CT_N];
    float s = 0.f;
#pragma unroll
    for (int c = 0; c < CT_N / 4; c++) {
        float4 v = p[c];
        s += v.x + v.y + v.z + v.w;
    }
    sm[tid] = logf(s) - g_diag[row];
    __syncthreads();
#pragma unroll
    for (int o = 128; o; o >>= 1) {
        if (tid < o) sm[tid] += sm[tid + o];
        __syncthreads();
    }
    if (tid == 0) {
        g_blocksum[blockIdx.x] = sm[0];
        __threadfence();
        unsigned int prev = atomicAdd(&g_ticket, 1u);
        amLast = (prev == 15u);
    }
    __syncthreads();
    if (amLast && tid == 0) {
        float tot = 0.f;
#pragma unroll
        for (int b = 0; b < 16; b++) tot += g_blocksum[b];   // fixed order: deterministic
        out[0] = tot * (1.0f / N_ROWS);
        g_ticket = 0u;                                        // reset for next graph replay
    }
}

// ---------------------------------------------------------------------------
extern "C" void kernel_launch(void* const* d_in, const int* in_sizes, int n_in,
                              void* d_out, int out_size) {
    const float* x = (const float*)d_in[0];
    const float* t = (const float*)d_in[1];
    const float* h = (const float*)d_in[2];
    float* out = (float*)d_out;

    cudaFuncSetAttribute(sim_fp8_kernel,
                         cudaFuncAttributeMaxDynamicSharedMemorySize, SMEM_TOTAL);

    norm_convert_kernel<<<(3 * N_ROWS) / 8, 256>>>(x, t, h);

    dim3 grid(CT_N, RT_N);
    sim_fp8_kernel<<<grid, NTHREADS, SMEM_TOTAL>>>();

    rowloss_kernel<<<N_ROWS / 256, 256>>>(out);
}

// round 12
// speedup vs baseline: 2.5266x; 1.0002x over previous
#include <cuda_runtime.h>
#include <cuda_bf16.h>
#include <cuda_fp16.h>
#include <math.h>
#include <stdint.h>

#define N_ROWS   4096
#define D_DIM    1024
#define TEMP_INV 20.0f
#define EPS_N    1e-8f
#define QSCALE   16.0f
#define ISC2     (1.0f / (QSCALE * QSCALE))

// GEMM tiling (fp8 e4m3; K in bytes == elements) — round-7 proven config
#define BM 128
#define BN 128
#define BK 128
#define NKC (D_DIM / BK)         // 8 chunks
#define NSTAGE 3
#define CT_N (2 * N_ROWS / BN)   // 64 col tiles
#define RT_N (N_ROWS / BM)       // 32 row tiles
#define ROWB 144                 // 128B data + 16B pad
#define NTHREADS 256

#define STAGE_BYTES ((BM + BN) * ROWB)             // 36864
#define SM_SRED     (NSTAGE * STAGE_BYTES)         // 110592
#define SMEM_TOTAL  (SM_SRED + BM * 4 * 4)         // 112640 (2 CTAs/SM)

// Scratch
__device__ uint8_t g_q[3][(size_t)N_ROWS * D_DIM];
__device__ float g_partial[(size_t)N_ROWS * CT_N];
__device__ float g_diag[N_ROWS];
__device__ float g_blocksum[16];
__device__ unsigned int g_ticket;    // zero-init; self-resets each replay

// ---------------------------------------------------------------------------
__device__ __forceinline__ uint32_t smem_u32(const void* p) {
    uint32_t a;
    asm("{ .reg .u64 t; cvta.to.shared.u64 t, %1; cvt.u32.u64 %0, t; }"
        : "=r"(a) : "l"(p));
    return a;
}

#define LDSM_X4(r, addr) \
    asm volatile("ldmatrix.sync.aligned.m8n8.x4.shared.b16 {%0,%1,%2,%3}, [%4];" \
                 : "=r"((r)[0]), "=r"((r)[1]), "=r"((r)[2]), "=r"((r)[3]) : "r"(addr))

#define MMA_FP8_H(d, a, b) \
    asm volatile("mma.sync.aligned.m16n8k32.row.col.f16.e4m3.e4m3.f16 " \
                 "{%0,%1}, {%2,%3,%4,%5}, {%6,%7}, {%0,%1};" \
                 : "+r"((d)[0]), "+r"((d)[1]) \
                 : "r"((a)[0]), "r"((a)[1]), "r"((a)[2]), "r"((a)[3]), \
                   "r"((b)[0]), "r"((b)[1]))

#define CP_ASYNC16(so, gp) \
    asm volatile("cp.async.cg.shared.global [%0], [%1], 16;" \
                 :: "r"(so), "l"(__cvta_generic_to_global(gp)))
#define CP_COMMIT()  asm volatile("cp.async.commit_group;" ::: "memory")
#define CP_WAIT(n)   asm volatile("cp.async.wait_group %0;" :: "n"(n) : "memory")

__device__ __forceinline__ uint32_t pack4_e4m3(float4 v) {
    uint16_t lo, hi;
    asm("cvt.rn.satfinite.e4m3x2.f32 %0, %1, %2;" : "=h"(lo) : "f"(v.y), "f"(v.x));
    asm("cvt.rn.satfinite.e4m3x2.f32 %0, %1, %2;" : "=h"(hi) : "f"(v.w), "f"(v.z));
    return (uint32_t)lo | ((uint32_t)hi << 16);
}

// ---------------------------------------------------------------------------
// Kernel 1: warp-per-row normalize + fp8 convert, TWO-PASS (low regs, high occ).
// Pass 1 accumulates sum-of-squares (no value retention); pass 2 re-reads the
// row (L2-hot) and converts. ~24 regs -> ~full occupancy.
// ---------------------------------------------------------------------------
__global__ void __launch_bounds__(256) norm_convert_kernel(const float* __restrict__ x,
                                                           const float* __restrict__ t,
                                                           const float* __restrict__ h) {
    int warp = (blockIdx.x * blockDim.x + threadIdx.x) >> 5;
    int lane = threadIdx.x & 31;
    if (warp >= 3 * N_ROWS) return;
    int mat = warp / N_ROWS;
    int row = warp - mat * N_ROWS;
    const float* src = (mat == 0) ? x : (mat == 1 ? t : h);
    const float4* p = (const float4*)(src + (size_t)row * D_DIM);

    float s = 0.f;
#pragma unroll
    for (int i = 0; i < 8; i++) {
        float4 v = p[lane + i * 32];
        s = fmaf(v.x, v.x, s);
        s = fmaf(v.y, v.y, s);
        s = fmaf(v.z, v.z, s);
        s = fmaf(v.w, v.w, s);
    }
#pragma unroll
    for (int o = 16; o; o >>= 1) s += __shfl_xor_sync(0xffffffffu, s, o);
    float inv = 1.0f / fmaxf(sqrtf(s), EPS_N);
    float sc = ((mat == 0) ? inv * TEMP_INV : inv) * QSCALE;

    uint32_t* dst = (uint32_t*)(&g_q[mat][(size_t)row * D_DIM]);
#pragma unroll
    for (int i = 0; i < 8; i++) {
        float4 v = p[lane + i * 32];   // L2 hit: same warp read it moments ago
        float4 w;
        w.x = v.x * sc; w.y = v.y * sc; w.z = v.z * sc; w.w = v.w * sc;
        dst[lane + i * 32] = pack4_e4m3(w);
    }
}

// ---------------------------------------------------------------------------
// Kernel 2: e4m3 GEMM (f16 acc), CTA 128x128, 256 threads (2Mx4N warps),
// BK=128, 3-stage cp.async, fragment double-buffering, 2 CTAs/SM. (round 7)
// ---------------------------------------------------------------------------
__global__ void __launch_bounds__(NTHREADS, 2) sim_fp8_kernel() {
    extern __shared__ __align__(16) char dsm[];
    const int tid = threadIdx.x;
    const int lane = tid & 31;
    const int wid = tid >> 5;
    const int wm = wid & 1;            // 0..1 -> 64 rows
    const int wn = wid >> 1;           // 0..3 -> 32 cols

    const int ct = blockIdx.x;         // 0..63
    const int rt = blockIdx.y;         // 0..31
    const int rbase = rt * BM;
    const int cbase = ct * BN;
    const bool isNeg = (cbase >= N_ROWS);
    const uint8_t* Bmat = isNeg ? g_q[2] : g_q[1];
    const int cloc = isNeg ? (cbase - N_ROWS) : cbase;

    const uint8_t* Ag = g_q[0] + (size_t)rbase * D_DIM;
    const uint8_t* Bg = Bmat + (size_t)cloc * D_DIM;

    uint32_t aSm[4], aGo[4], bSm[4], bGo[4];
#pragma unroll
    for (int q = 0; q < 4; q++) {
        int slot = tid + q * NTHREADS;
        int r = slot >> 3, sg = (slot & 7) * 16;
        aSm[q] = (uint32_t)(r * ROWB + sg);
        aGo[q] = (uint32_t)(r * D_DIM + sg);
        bSm[q] = (uint32_t)(BM * ROWB + r * ROWB + sg);
        bGo[q] = (uint32_t)(r * D_DIM + sg);
    }
    uint32_t stageBase[NSTAGE];
#pragma unroll
    for (int s = 0; s < NSTAGE; s++) stageBase[s] = smem_u32(dsm + s * STAGE_BYTES);

#define LOAD_CHUNK(c, st)                                       \
    do {                                                        \
        const uint32_t k0 = (c) * BK;                           \
        const uint32_t sb_ = stageBase[st];                     \
        CP_ASYNC16(sb_ + aSm[0], Ag + aGo[0] + k0);             \
        CP_ASYNC16(sb_ + aSm[1], Ag + aGo[1] + k0);             \
        CP_ASYNC16(sb_ + aSm[2], Ag + aGo[2] + k0);             \
        CP_ASYNC16(sb_ + aSm[3], Ag + aGo[3] + k0);             \
        CP_ASYNC16(sb_ + bSm[0], Bg + bGo[0] + k0);             \
        CP_ASYNC16(sb_ + bSm[1], Bg + bGo[1] + k0);             \
        CP_ASYNC16(sb_ + bSm[2], Bg + bGo[2] + k0);             \
        CP_ASYNC16(sb_ + bSm[3], Bg + bGo[3] + k0);             \
        CP_COMMIT();                                            \
    } while (0)

    uint32_t acc[4][4][2];
#pragma unroll
    for (int i = 0; i < 4; i++)
#pragma unroll
        for (int j = 0; j < 4; j++) { acc[i][j][0] = 0u; acc[i][j][1] = 0u; }

    LOAD_CHUNK(0, 0);
    LOAD_CHUNK(1, 1);

    const int aRow = lane & 15;
    const int aSeg = (lane >> 4) * 16;
    const int bRow = ((lane >> 4) ? 8 : 0) + (lane & 7);
    const int bSeg = ((lane >> 3) & 1) * 16;

    uint32_t afr[2][4][4], bfr[2][4][2];

#define LOAD_FRAGS(buf_, base_, kso_)                                        \
    do {                                                                     \
        _Pragma("unroll")                                                    \
        for (int mt = 0; mt < 4; mt++) {                                     \
            int row = wm * 64 + mt * 16 + aRow;                              \
            LDSM_X4(afr[buf_][mt], (base_) + row * ROWB + (kso_) + aSeg);    \
        }                                                                    \
        _Pragma("unroll")                                                    \
        for (int np = 0; np < 2; np++) {                                     \
            int nrow = wn * 32 + np * 16 + bRow;                             \
            uint32_t r_[4];                                                  \
            LDSM_X4(r_, (base_) + BM * ROWB + nrow * ROWB + (kso_) + bSeg);  \
            bfr[buf_][np * 2 + 0][0] = r_[0];                                \
            bfr[buf_][np * 2 + 0][1] = r_[1];                                \
            bfr[buf_][np * 2 + 1][0] = r_[2];                                \
            bfr[buf_][np * 2 + 1][1] = r_[3];                                \
        }                                                                    \
    } while (0)

    for (int c = 0; c < NKC; c++) {
        CP_WAIT(1);
        __syncthreads();
        if (c + 2 < NKC) LOAD_CHUNK(c + 2, (c + 2) % 3);
        else CP_COMMIT();

        const uint32_t sBase = stageBase[c % 3];
        LOAD_FRAGS(0, sBase, 0);
#pragma unroll
        for (int ks = 0; ks < 4; ks++) {
            const int cur = ks & 1;
            if (ks < 3) LOAD_FRAGS(cur ^ 1, sBase, (ks + 1) * 32);
#pragma unroll
            for (int mt = 0; mt < 4; mt++)
#pragma unroll
                for (int nt = 0; nt < 4; nt++)
                    MMA_FP8_H(acc[mt][nt], afr[cur][mt], bfr[cur][nt]);
        }
    }

    // Epilogue
    const int g = lane >> 2;
    const int t2 = (lane & 3) * 2;
    const int diagOff = isNeg ? N_ROWS : 0;
    float* sred = (float*)(dsm + SM_SRED);

#pragma unroll
    for (int mt = 0; mt < 4; mt++) {
        const int gi0 = rbase + wm * 64 + mt * 16 + g;
        const int gi1 = gi0 + 8;
        const int d0 = gi0 + diagOff;
        const int d1 = gi1 + diagOff;
        float s0 = 0.f, s1 = 0.f;
#pragma unroll
        for (int nt = 0; nt < 4; nt++) {
            const int gc = cbase + wn * 32 + nt * 8 + t2;
            __half2 lo = *(__half2*)&acc[mt][nt][0];
            __half2 hi = *(__half2*)&acc[mt][nt][1];
            float v0 = __half2float(lo.x) * ISC2;
            float v1 = __half2float(lo.y) * ISC2;
            float v2 = __half2float(hi.x) * ISC2;
            float v3 = __half2float(hi.y) * ISC2;
            if (gc == d0)     { if (isNeg) v0 += 1.f; else g_diag[gi0] = v0; }
            if (gc + 1 == d0) { if (isNeg) v1 += 1.f; else g_diag[gi0] = v1; }
            if (gc == d1)     { if (isNeg) v2 += 1.f; else g_diag[gi1] = v2; }
            if (gc + 1 == d1) { if (isNeg) v3 += 1.f; else g_diag[gi1] = v3; }
            s0 += __expf(v0) + __expf(v1);
            s1 += __expf(v2) + __expf(v3);
        }
        s0 += __shfl_xor_sync(0xffffffffu, s0, 1);
        s0 += __shfl_xor_sync(0xffffffffu, s0, 2);
        s1 += __shfl_xor_sync(0xffffffffu, s1, 1);
        s1 += __shfl_xor_sync(0xffffffffu, s1, 2);
        if ((lane & 3) == 0) {
            sred[(wm * 64 + mt * 16 + g) * 4 + wn] = s0;
            sred[(wm * 64 + mt * 16 + g + 8) * 4 + wn] = s1;
        }
    }
    __syncthreads();
    if (tid < BM) {
        float s = sred[tid * 4] + sred[tid * 4 + 1] + sred[tid * 4 + 2] + sred[tid * 4 + 3];
        g_partial[(size_t)(rbase + tid) * CT_N + ct] = s;
    }
}

// ---------------------------------------------------------------------------
// Kernel 3: fused per-row loss + final reduction (self-resetting ticket).
// ---------------------------------------------------------------------------
__global__ void __launch_bounds__(256) rowloss_kernel(float* __restrict__ out) {
    __shared__ float sm[256];
    __shared__ bool amLast;
    const int tid = threadIdx.x;
    const int row = blockIdx.x * 256 + tid;
    const float4* p = (const float4*)&g_partial[(size_t)row * CT_N];
    float s = 0.f;
#pragma unroll
    for (int c = 0; c < CT_N / 4; c++) {
        float4 v = p[c];
        s += v.x + v.y + v.z + v.w;
    }
    sm[tid] = logf(s) - g_diag[row];
    __syncthreads();
#pragma unroll
    for (int o = 128; o; o >>= 1) {
        if (tid < o) sm[tid] += sm[tid + o];
        __syncthreads();
    }
    if (tid == 0) {
        g_blocksum[blockIdx.x] = sm[0];
        __threadfence();
        unsigned int prev = atomicAdd(&g_ticket, 1u);
        amLast = (prev == 15u);
    }
    __syncthreads();
    if (amLast && tid == 0) {
        float tot = 0.f;
#pragma unroll
        for (int b = 0; b < 16; b++) tot += g_blocksum[b];   // fixed order: deterministic
        out[0] = tot * (1.0f / N_ROWS);
        g_ticket = 0u;                                        // reset for next replay
    }
}

// ---------------------------------------------------------------------------
extern "C" void kernel_launch(void* const* d_in, const int* in_sizes, int n_in,
                              void* d_out, int out_size) {
    const float* x = (const float*)d_in[0];
    const float* t = (const float*)d_in[1];
    const float* h = (const float*)d_in[2];
    float* out = (float*)d_out;

    cudaFuncSetAttribute(sim_fp8_kernel,
                         cudaFuncAttributeMaxDynamicSharedMemorySize, SMEM_TOTAL);

    norm_convert_kernel<<<(3 * N_ROWS) / 8, 256>>>(x, t, h);

    dim3 grid(CT_N, RT_N);
    sim_fp8_kernel<<<grid, NTHREADS, SMEM_TOTAL>>>();

    rowloss_kernel<<<N_ROWS / 256, 256>>>(out);
}